// round 7
// baseline (speedup 1.0000x reference)
#include <cuda_runtime.h>
#include <cstddef>

#define C_    256
#define HW_   16384
#define B_    32
#define F_    256

#define P_    32          // positions per tile
#define RP_   36          // padded row stride (words): conflict-free rows + LDS.128
#define SPW_  36          // spart row stride
#define TPC_  8           // tiles per CTA
#define NB_   64          // CTAs per batch
#define NSLOT_ 3          // smem ring slots (depth-2 prefetch)

// Scratch (no allocs allowed)
__device__ float g_part[(size_t)B_ * NB_ * C_];   // 2 MB
__device__ float g_z[B_ * NB_];

// ---------------------------------------------------------------------------
__device__ __forceinline__ unsigned smem_u32(const void* p) {
    return (unsigned)__cvta_generic_to_shared(p);
}
__device__ __forceinline__ void cp16(unsigned dst, const float* src) {
    asm volatile("cp.async.cg.shared.global [%0], [%1], 16;" :: "r"(dst), "l"(src));
}
__device__ __forceinline__ void cp_commit() {
    asm volatile("cp.async.commit_group;");
}
__device__ __forceinline__ void cp_wait0() {
    asm volatile("cp.async.wait_group 0;");
}
__device__ __forceinline__ void cp_wait1() {
    asm volatile("cp.async.wait_group 1;");
}

// ---------------------------------------------------------------------------
// Pass 1: single HBM pass. 2 CTAs/SM, 3-slot ring, depth-2 cp.async prefetch.
// Per tile: [wait oldest][bar][issue t+2][logits][bar][exp (all warps)][bar][context]
// ---------------------------------------------------------------------------
__global__ __launch_bounds__(256, 2)
void ctx_pass1(const float* __restrict__ x,
               const float* __restrict__ mask_w,
               const float* __restrict__ mask_b) {
    extern __shared__ float sm[];              // NSLOT_ * C_*RP_ floats = 110592 B
    __shared__ float spart[8 * SPW_];
    __shared__ __align__(16) float se[P_];
    __shared__ float zacc[8];

    const int b = blockIdx.y, blk = blockIdx.x, t = threadIdx.x;
    const int w = t >> 5, lane = t & 31;
    const float* xb = x + (size_t)b * C_ * HW_ + (size_t)blk * (TPC_ * P_);
    const float mb = mask_b[0];

    // mask weights for this warp's 32 channels -> registers (shuffle broadcast)
    float wv[32];
    {
        float myw = mask_w[w * 32 + lane];
#pragma unroll
        for (int cc = 0; cc < 32; cc++)
            wv[cc] = __shfl_sync(0xffffffffu, myw, cc);
    }

    const unsigned smbase = smem_u32(sm);

    auto load_tile = [&](int tile, int slot) {
        const unsigned dbase = smbase + (unsigned)(slot * C_ * RP_) * 4u;
        const float* src0 = xb + tile * P_;
#pragma unroll
        for (int i = 0; i < 8; i++) {
            int s = i * 256 + t;
            int c = s >> 3, q = s & 7;
            cp16(dbase + (unsigned)(c * RP_ + q * 4) * 4u,
                 src0 + (size_t)c * HW_ + q * 4);
        }
    };

    load_tile(0, 0); cp_commit();
    load_tile(1, 1); cp_commit();

    float acc = 0.f;     // per-thread: channel t partial context
    float zw  = 0.f;     // per-warp Z partial (uniform across lanes)

    int slot = 0;
#pragma unroll 1
    for (int tile = 0; tile < TPC_; tile++) {
        if (tile < TPC_ - 1) cp_wait1();   // oldest group (tile) done
        else                 cp_wait0();
        __syncthreads();                   // visibility + slot (tile+2)%3 released

        if (tile + 2 < TPC_) {
            int ns = slot + 2; if (ns >= NSLOT_) ns -= NSLOT_;
            load_tile(tile + 2, ns);
            cp_commit();
        }

        const float* buf = sm + slot * C_ * RP_;

        // logit partials: warp w covers channels [32w,32w+32), lane = position
        float lacc = 0.f;
#pragma unroll
        for (int cc = 0; cc < 32; cc++)
            lacc += buf[(w * 32 + cc) * RP_ + lane] * wv[cc];
        spart[w * SPW_ + lane] = lacc;
        __syncthreads();

        // exp phase, all warps in parallel: warp w -> positions 4w..4w+3
        {
            int gi = lane >> 2, pj = lane & 3;
            float v = spart[gi * SPW_ + 4 * w + pj];
            v += __shfl_xor_sync(0xffffffffu, v, 4);
            v += __shfl_xor_sync(0xffffffffu, v, 8);
            v += __shfl_xor_sync(0xffffffffu, v, 16);
            float e = __expf(v + mb);
            if (lane < 4) se[4 * w + lane] = e;
            float z = e;
            z += __shfl_xor_sync(0xffffffffu, z, 1);
            z += __shfl_xor_sync(0xffffffffu, z, 2);
            zw += z;
        }
        __syncthreads();

        // context accumulation: thread t = channel t (stride-36 rows, conflict-free)
        const float4* rowv = reinterpret_cast<const float4*>(buf + t * RP_);
        const float4* sev  = reinterpret_cast<const float4*>(se);
        float a0 = 0.f, a1 = 0.f;
#pragma unroll
        for (int pp = 0; pp < 8; pp++) {
            float4 xv = rowv[pp], ev = sev[pp];
            a0 += xv.x * ev.x + xv.y * ev.y;
            a1 += xv.z * ev.z + xv.w * ev.w;
        }
        acc += a0 + a1;

        slot++; if (slot >= NSLOT_) slot = 0;
    }

    const int idx = b * NB_ + blk;
    g_part[(size_t)idx * C_ + t] = acc;
    if (lane == 0) zacc[w] = zw;
    __syncthreads();
    if (t == 0) {
        float z = 0.f;
#pragma unroll
        for (int i = 0; i < 8; i++) z += zacc[i];
        g_z[idx] = z;
    }
}

// ---------------------------------------------------------------------------
// Pass 2: combine + fused tail (warp-cooperative matvecs); center tap inlined
// ---------------------------------------------------------------------------
__global__ __launch_bounds__(256)
void fused_tail(const float* __restrict__ cm1_w, const float* __restrict__ cm1_b,
                const float* __restrict__ ln_g,  const float* __restrict__ ln_b,
                const float* __restrict__ cm2_w, const float* __restrict__ cm2_b,
                const float* __restrict__ out_w, const float* __restrict__ out_b,
                const float* __restrict__ att_w, const float* __restrict__ att_b,
                float* __restrict__ out) {
    __shared__ float sv[C_];
    __shared__ float sh[C_];
    __shared__ float sred[20];

    const int b = blockIdx.x, t = threadIdx.x;
    const int w = t >> 5, lane = t & 31;

    if (t < 32) {
        float zz = g_z[b * NB_ + t] + g_z[b * NB_ + 32 + t];
#pragma unroll
        for (int o = 16; o; o >>= 1) zz += __shfl_xor_sync(0xffffffffu, zz, o);
        if (t == 0) sred[0] = 1.f / zz;
    }
    __syncthreads();
    const float invZ = sred[0];

    // combine partial contexts (coalesced per k, L2-resident)
    float acc = 0.f;
    const float* gp = g_part + (size_t)b * NB_ * C_ + t;
#pragma unroll 8
    for (int k = 0; k < NB_; k++) acc += gp[(size_t)k * C_];
    sv[t] = acc * invZ;
    __syncthreads();

    // h = cm1_w @ ctx + cm1_b  (warp-coop, 2 outputs interleaved)
#pragma unroll 2
    for (int i = 0; i < 16; i++) {
        int o0 = w * 32 + 2 * i, o1 = o0 + 1;
        const float* r0 = cm1_w + (size_t)o0 * C_;
        const float* r1 = cm1_w + (size_t)o1 * C_;
        float p0 = 0.f, p1 = 0.f;
#pragma unroll
        for (int j = 0; j < 8; j++) {
            float v = sv[j * 32 + lane];
            p0 += r0[j * 32 + lane] * v;
            p1 += r1[j * 32 + lane] * v;
        }
#pragma unroll
        for (int o = 16; o; o >>= 1) {
            p0 += __shfl_xor_sync(0xffffffffu, p0, o);
            p1 += __shfl_xor_sync(0xffffffffu, p1, o);
        }
        if (lane == 0) { sh[o0] = p0 + cm1_b[o0]; sh[o1] = p1 + cm1_b[o1]; }
    }
    __syncthreads();

    // LayerNorm over C + ReLU
    float h = sh[t];
    float sum = h, sq = h * h;
#pragma unroll
    for (int o = 16; o; o >>= 1) {
        sum += __shfl_xor_sync(0xffffffffu, sum, o);
        sq  += __shfl_xor_sync(0xffffffffu, sq,  o);
    }
    if (lane == 0) { sred[2 + w] = sum; sred[10 + w] = sq; }
    __syncthreads();
    if (t == 0) {
        float a = 0.f, bb = 0.f;
#pragma unroll
        for (int i = 0; i < 8; i++) { a += sred[2 + i]; bb += sred[10 + i]; }
        sred[0] = a; sred[1] = bb;
    }
    __syncthreads();
    {
        const float mu  = sred[0] * (1.f / C_);
        const float var = sred[1] * (1.f / C_) - mu * mu;
        h = (h - mu) * rsqrtf(var + 1e-5f) * ln_g[t] + ln_b[t];
        h = fmaxf(h, 0.f);
    }
    __syncthreads();
    sv[t] = h;
    __syncthreads();

    // h2 = cm2_w @ h + cm2_b
#pragma unroll 2
    for (int i = 0; i < 16; i++) {
        int o0 = w * 32 + 2 * i, o1 = o0 + 1;
        const float* r0 = cm2_w + (size_t)o0 * C_;
        const float* r1 = cm2_w + (size_t)o1 * C_;
        float p0 = 0.f, p1 = 0.f;
#pragma unroll
        for (int j = 0; j < 8; j++) {
            float v = sv[j * 32 + lane];
            p0 += r0[j * 32 + lane] * v;
            p1 += r1[j * 32 + lane] * v;
        }
#pragma unroll
        for (int o = 16; o; o >>= 1) {
            p0 += __shfl_xor_sync(0xffffffffu, p0, o);
            p1 += __shfl_xor_sync(0xffffffffu, p1, o);
        }
        if (lane == 0) { sh[o0] = p0 + cm2_b[o0]; sh[o1] = p1 + cm2_b[o1]; }
    }
    __syncthreads();
    {
        float ix = 1.f / (1.f + __expf(-sh[t]));
        __syncthreads();
        sv[t] = ix;
    }
    __syncthreads();

    // out = center-tap conv (direct from out_w[:,:,2,2]), gated by sigmoid(att)
#pragma unroll 2
    for (int i = 0; i < 32; i++) {
        int o = w * 32 + i;
        const float* rc = out_w + (size_t)o * C_ * 25 + 12;
        const float* ra = att_w + (size_t)o * C_;
        float po = 0.f, pa = 0.f;
#pragma unroll
        for (int j = 0; j < 8; j++) {
            int c = j * 32 + lane;
            float v = sv[c];
            po += rc[(size_t)c * 25] * v;
            pa += ra[c] * v;
        }
#pragma unroll
        for (int off = 16; off; off >>= 1) {
            po += __shfl_xor_sync(0xffffffffu, po, off);
            pa += __shfl_xor_sync(0xffffffffu, pa, off);
        }
        if (lane == 0) {
            float ov = po + out_b[o];
            float av = 1.f / (1.f + __expf(-(pa + att_b[o])));
            out[b * F_ + o] = av * ov;
        }
    }
}

extern "C" void kernel_launch(void* const* d_in, const int* in_sizes, int n_in,
                              void* d_out, int out_size) {
    const float* x      = (const float*)d_in[0];
    const float* mask_w = (const float*)d_in[1];
    const float* mask_b = (const float*)d_in[2];
    const float* cm1_w  = (const float*)d_in[3];
    const float* cm1_b  = (const float*)d_in[4];
    const float* ln_g   = (const float*)d_in[5];
    const float* ln_b   = (const float*)d_in[6];
    const float* cm2_w  = (const float*)d_in[7];
    const float* cm2_b  = (const float*)d_in[8];
    const float* out_w  = (const float*)d_in[9];
    const float* out_b  = (const float*)d_in[10];
    const float* att_w  = (const float*)d_in[11];
    const float* att_b  = (const float*)d_in[12];
    float* out = (float*)d_out;

    const int smem1 = NSLOT_ * C_ * RP_ * (int)sizeof(float);  // 110592 B
    cudaFuncSetAttribute(ctx_pass1, cudaFuncAttributeMaxDynamicSharedMemorySize, smem1);

    ctx_pass1<<<dim3(NB_, B_), 256, smem1>>>(x, mask_w, mask_b);
    fused_tail<<<B_, 256>>>(cm1_w, cm1_b, ln_g, ln_b, cm2_w, cm2_b,
                            out_w, out_b, att_w, att_b, out);
}

// round 8
// speedup vs baseline: 1.5689x; 1.5689x over previous
#include <cuda_runtime.h>
#include <cstddef>

#define C_    256
#define HW_   16384
#define B_    32
#define F_    256

#define P_    32
#define RP_   36
#define SPW_  36
#define TPC_  8
#define NB_   64
#define NSLOT_ 3

// Scratch (no allocs allowed)
__device__ float g_part[(size_t)B_ * NB_ * C_];   // 2 MB
__device__ float g_z[B_ * NB_];
__device__ float g_h1[B_ * C_];
__device__ float g_ix[B_ * C_];

// ---------------------------------------------------------------------------
__device__ __forceinline__ unsigned smem_u32(const void* p) {
    return (unsigned)__cvta_generic_to_shared(p);
}
__device__ __forceinline__ void cp16(unsigned dst, const float* src) {
    asm volatile("cp.async.cg.shared.global [%0], [%1], 16;" :: "r"(dst), "l"(src));
}
__device__ __forceinline__ void cp_commit() {
    asm volatile("cp.async.commit_group;");
}
__device__ __forceinline__ void cp_wait0() {
    asm volatile("cp.async.wait_group 0;");
}
__device__ __forceinline__ void cp_wait1() {
    asm volatile("cp.async.wait_group 1;");
}

// ---------------------------------------------------------------------------
// Pass 1 (unchanged from R7): single HBM pass, 2 CTAs/SM, 3-slot ring, depth-2
// ---------------------------------------------------------------------------
__global__ __launch_bounds__(256, 2)
void ctx_pass1(const float* __restrict__ x,
               const float* __restrict__ mask_w,
               const float* __restrict__ mask_b) {
    extern __shared__ float sm[];
    __shared__ float spart[8 * SPW_];
    __shared__ __align__(16) float se[P_];
    __shared__ float zacc[8];

    const int b = blockIdx.y, blk = blockIdx.x, t = threadIdx.x;
    const int w = t >> 5, lane = t & 31;
    const float* xb = x + (size_t)b * C_ * HW_ + (size_t)blk * (TPC_ * P_);
    const float mb = mask_b[0];

    float wv[32];
    {
        float myw = mask_w[w * 32 + lane];
#pragma unroll
        for (int cc = 0; cc < 32; cc++)
            wv[cc] = __shfl_sync(0xffffffffu, myw, cc);
    }

    const unsigned smbase = smem_u32(sm);

    auto load_tile = [&](int tile, int slot) {
        const unsigned dbase = smbase + (unsigned)(slot * C_ * RP_) * 4u;
        const float* src0 = xb + tile * P_;
#pragma unroll
        for (int i = 0; i < 8; i++) {
            int s = i * 256 + t;
            int c = s >> 3, q = s & 7;
            cp16(dbase + (unsigned)(c * RP_ + q * 4) * 4u,
                 src0 + (size_t)c * HW_ + q * 4);
        }
    };

    load_tile(0, 0); cp_commit();
    load_tile(1, 1); cp_commit();

    float acc = 0.f;
    float zw  = 0.f;

    int slot = 0;
#pragma unroll 1
    for (int tile = 0; tile < TPC_; tile++) {
        if (tile < TPC_ - 1) cp_wait1();
        else                 cp_wait0();
        __syncthreads();

        if (tile + 2 < TPC_) {
            int ns = slot + 2; if (ns >= NSLOT_) ns -= NSLOT_;
            load_tile(tile + 2, ns);
            cp_commit();
        }

        const float* buf = sm + slot * C_ * RP_;

        float lacc = 0.f;
#pragma unroll
        for (int cc = 0; cc < 32; cc++)
            lacc += buf[(w * 32 + cc) * RP_ + lane] * wv[cc];
        spart[w * SPW_ + lane] = lacc;
        __syncthreads();

        {
            int gi = lane >> 2, pj = lane & 3;
            float v = spart[gi * SPW_ + 4 * w + pj];
            v += __shfl_xor_sync(0xffffffffu, v, 4);
            v += __shfl_xor_sync(0xffffffffu, v, 8);
            v += __shfl_xor_sync(0xffffffffu, v, 16);
            float e = __expf(v + mb);
            if (lane < 4) se[4 * w + lane] = e;
            float z = e;
            z += __shfl_xor_sync(0xffffffffu, z, 1);
            z += __shfl_xor_sync(0xffffffffu, z, 2);
            zw += z;
        }
        __syncthreads();

        const float4* rowv = reinterpret_cast<const float4*>(buf + t * RP_);
        const float4* sev  = reinterpret_cast<const float4*>(se);
        float a0 = 0.f, a1 = 0.f;
#pragma unroll
        for (int pp = 0; pp < 8; pp++) {
            float4 xv = rowv[pp], ev = sev[pp];
            a0 += xv.x * ev.x + xv.y * ev.y;
            a1 += xv.z * ev.z + xv.w * ev.w;
        }
        acc += a0 + a1;

        slot++; if (slot >= NSLOT_) slot = 0;
    }

    const int idx = b * NB_ + blk;
    g_part[(size_t)idx * C_ + t] = acc;
    if (lane == 0) zacc[w] = zw;
    __syncthreads();
    if (t == 0) {
        float z = 0.f;
#pragma unroll
        for (int i = 0; i < 8; i++) z += zacc[i];
        g_z[idx] = z;
    }
}

// ---------------------------------------------------------------------------
// mv1: grid(4, B). Each CTA: combine ctx (redundant, L2-hot) + 64 rows of cm1.
// ---------------------------------------------------------------------------
__global__ __launch_bounds__(256)
void mv1_kernel(const float* __restrict__ cm1_w, const float* __restrict__ cm1_b) {
    __shared__ float sctx[C_];
    __shared__ float sred[1];

    const int b = blockIdx.y, rc = blockIdx.x, t = threadIdx.x;
    const int w = t >> 5, lane = t & 31;

    if (t < 32) {
        float zz = g_z[b * NB_ + t] + g_z[b * NB_ + 32 + t];
#pragma unroll
        for (int o = 16; o; o >>= 1) zz += __shfl_xor_sync(0xffffffffu, zz, o);
        if (t == 0) sred[0] = 1.f / zz;
    }

    // combine: thread t = channel t (coalesced over k)
    float acc = 0.f;
    const float* gp = g_part + (size_t)b * NB_ * C_ + t;
#pragma unroll 8
    for (int k = 0; k < NB_; k++) acc += gp[(size_t)k * C_];
    __syncthreads();
    sctx[t] = acc * sred[0];
    __syncthreads();

    // 64 rows: warp w -> rows rc*64 + w*8 + {0..7}, 2 interleaved
#pragma unroll
    for (int i = 0; i < 4; i++) {
        int o0 = rc * 64 + w * 8 + 2 * i, o1 = o0 + 1;
        const float* r0 = cm1_w + (size_t)o0 * C_;
        const float* r1 = cm1_w + (size_t)o1 * C_;
        float p0 = 0.f, p1 = 0.f;
#pragma unroll
        for (int j = 0; j < 8; j++) {
            float v = sctx[j * 32 + lane];
            p0 += r0[j * 32 + lane] * v;
            p1 += r1[j * 32 + lane] * v;
        }
#pragma unroll
        for (int o = 16; o; o >>= 1) {
            p0 += __shfl_xor_sync(0xffffffffu, p0, o);
            p1 += __shfl_xor_sync(0xffffffffu, p1, o);
        }
        if (lane == 0) {
            g_h1[b * C_ + o0] = p0 + cm1_b[o0];
            g_h1[b * C_ + o1] = p1 + cm1_b[o1];
        }
    }
}

// ---------------------------------------------------------------------------
// mv2: grid(4, B). LN (redundant stats) + ReLU + 64 rows of cm2 + sigmoid.
// ---------------------------------------------------------------------------
__global__ __launch_bounds__(256)
void mv2_kernel(const float* __restrict__ ln_g,  const float* __restrict__ ln_b,
                const float* __restrict__ cm2_w, const float* __restrict__ cm2_b) {
    __shared__ float sh[C_];
    __shared__ float sred[18];

    const int b = blockIdx.y, rc = blockIdx.x, t = threadIdx.x;
    const int w = t >> 5, lane = t & 31;

    float h = g_h1[b * C_ + t];
    float sum = h, sq = h * h;
#pragma unroll
    for (int o = 16; o; o >>= 1) {
        sum += __shfl_xor_sync(0xffffffffu, sum, o);
        sq  += __shfl_xor_sync(0xffffffffu, sq,  o);
    }
    if (lane == 0) { sred[2 + w] = sum; sred[10 + w] = sq; }
    __syncthreads();
    if (t == 0) {
        float a = 0.f, bb = 0.f;
#pragma unroll
        for (int i = 0; i < 8; i++) { a += sred[2 + i]; bb += sred[10 + i]; }
        sred[0] = a; sred[1] = bb;
    }
    __syncthreads();
    {
        const float mu  = sred[0] * (1.f / C_);
        const float var = sred[1] * (1.f / C_) - mu * mu;
        h = (h - mu) * rsqrtf(var + 1e-5f) * ln_g[t] + ln_b[t];
        h = fmaxf(h, 0.f);
    }
    sh[t] = h;
    __syncthreads();

#pragma unroll
    for (int i = 0; i < 4; i++) {
        int o0 = rc * 64 + w * 8 + 2 * i, o1 = o0 + 1;
        const float* r0 = cm2_w + (size_t)o0 * C_;
        const float* r1 = cm2_w + (size_t)o1 * C_;
        float p0 = 0.f, p1 = 0.f;
#pragma unroll
        for (int j = 0; j < 8; j++) {
            float v = sh[j * 32 + lane];
            p0 += r0[j * 32 + lane] * v;
            p1 += r1[j * 32 + lane] * v;
        }
#pragma unroll
        for (int o = 16; o; o >>= 1) {
            p0 += __shfl_xor_sync(0xffffffffu, p0, o);
            p1 += __shfl_xor_sync(0xffffffffu, p1, o);
        }
        if (lane == 0) {
            g_ix[b * C_ + o0] = 1.f / (1.f + __expf(-(p0 + cm2_b[o0])));
            g_ix[b * C_ + o1] = 1.f / (1.f + __expf(-(p1 + cm2_b[o1])));
        }
    }
}

// ---------------------------------------------------------------------------
// gate: grid(128). CTA j owns features {2j, 2j+1} for all 32 batches.
// Weights staged in smem (att rows coalesced; taps gathered with MLP=2/thread,
// but 32K threads chip-wide hide it). Warp w handles batches 4w..4w+3.
// ---------------------------------------------------------------------------
__global__ __launch_bounds__(256)
void gate_kernel(const float* __restrict__ out_w, const float* __restrict__ out_b,
                 const float* __restrict__ att_w, const float* __restrict__ att_b,
                 float* __restrict__ out) {
    __shared__ float swa0[C_], swa1[C_], swc0[C_], swc1[C_];

    const int j = blockIdx.x, t = threadIdx.x;
    const int o0 = 2 * j, o1 = 2 * j + 1;
    const int w = t >> 5, lane = t & 31;

    swa0[t] = att_w[(size_t)o0 * C_ + t];
    swa1[t] = att_w[(size_t)o1 * C_ + t];
    swc0[t] = out_w[(size_t)o0 * C_ * 25 + (size_t)t * 25 + 12];
    swc1[t] = out_w[(size_t)o1 * C_ * 25 + (size_t)t * 25 + 12];
    __syncthreads();

#pragma unroll
    for (int bb = 0; bb < 4; bb++) {
        int b = w * 4 + bb;
        const float* ixp = g_ix + b * C_;
        float pa0 = 0.f, pa1 = 0.f, pc0 = 0.f, pc1 = 0.f;
#pragma unroll
        for (int k = 0; k < 8; k++) {
            int c = k * 32 + lane;
            float v = ixp[c];
            pa0 += swa0[c] * v;
            pa1 += swa1[c] * v;
            pc0 += swc0[c] * v;
            pc1 += swc1[c] * v;
        }
#pragma unroll
        for (int o = 16; o; o >>= 1) {
            pa0 += __shfl_xor_sync(0xffffffffu, pa0, o);
            pa1 += __shfl_xor_sync(0xffffffffu, pa1, o);
            pc0 += __shfl_xor_sync(0xffffffffu, pc0, o);
            pc1 += __shfl_xor_sync(0xffffffffu, pc1, o);
        }
        if (lane == 0) {
            float a0 = 1.f / (1.f + __expf(-(pa0 + att_b[o0])));
            float a1 = 1.f / (1.f + __expf(-(pa1 + att_b[o1])));
            out[b * F_ + o0] = a0 * (pc0 + out_b[o0]);
            out[b * F_ + o1] = a1 * (pc1 + out_b[o1]);
        }
    }
}

extern "C" void kernel_launch(void* const* d_in, const int* in_sizes, int n_in,
                              void* d_out, int out_size) {
    const float* x      = (const float*)d_in[0];
    const float* mask_w = (const float*)d_in[1];
    const float* mask_b = (const float*)d_in[2];
    const float* cm1_w  = (const float*)d_in[3];
    const float* cm1_b  = (const float*)d_in[4];
    const float* ln_g   = (const float*)d_in[5];
    const float* ln_b   = (const float*)d_in[6];
    const float* cm2_w  = (const float*)d_in[7];
    const float* cm2_b  = (const float*)d_in[8];
    const float* out_w  = (const float*)d_in[9];
    const float* out_b  = (const float*)d_in[10];
    const float* att_w  = (const float*)d_in[11];
    const float* att_b  = (const float*)d_in[12];
    float* out = (float*)d_out;

    const int smem1 = NSLOT_ * C_ * RP_ * (int)sizeof(float);  // 110592 B
    cudaFuncSetAttribute(ctx_pass1, cudaFuncAttributeMaxDynamicSharedMemorySize, smem1);

    ctx_pass1<<<dim3(NB_, B_), 256, smem1>>>(x, mask_w, mask_b);
    mv1_kernel<<<dim3(4, B_), 256>>>(cm1_w, cm1_b);
    mv2_kernel<<<dim3(4, B_), 256>>>(ln_g, ln_b, cm2_w, cm2_b);
    gate_kernel<<<128, 256>>>(out_w, out_b, att_w, att_b, out);
}

// round 9
// speedup vs baseline: 1.5743x; 1.0034x over previous
#include <cuda_runtime.h>
#include <cstddef>

#define C_    256
#define HW_   16384
#define B_    32
#define F_    256

#define P_    32
#define RP_   36
#define SPW_  36
#define TPC_  8
#define NB_   64
#define NSLOT_ 3

// Scratch (no allocs allowed)
__device__ float g_part[(size_t)B_ * NB_ * C_];   // 2 MB
__device__ float g_z[B_ * NB_];
__device__ float g_h1[B_ * C_];
__device__ float g_ix[B_ * C_];
__device__ float g_wc[F_ * C_];                   // packed center taps

// ---------------------------------------------------------------------------
__device__ __forceinline__ unsigned smem_u32(const void* p) {
    return (unsigned)__cvta_generic_to_shared(p);
}
__device__ __forceinline__ void cp16(unsigned dst, const float* src) {
    asm volatile("cp.async.cg.shared.global [%0], [%1], 16;" :: "r"(dst), "l"(src));
}
__device__ __forceinline__ void cp_commit() {
    asm volatile("cp.async.commit_group;");
}
__device__ __forceinline__ void cp_wait0() {
    asm volatile("cp.async.wait_group 0;");
}
__device__ __forceinline__ void cp_wait1() {
    asm volatile("cp.async.wait_group 1;");
}

// ---------------------------------------------------------------------------
// Pass 1: single HBM pass, 2 CTAs/SM, 3-slot ring, depth-2 prefetch.
// 2 bars/tile: exp phase is warp-redundant + warp-private (syncwarp only).
// Also packs out_w center taps (32 scattered loads/CTA, hidden by the stream).
// ---------------------------------------------------------------------------
__global__ __launch_bounds__(256, 2)
void ctx_pass1(const float* __restrict__ x,
               const float* __restrict__ mask_w,
               const float* __restrict__ mask_b,
               const float* __restrict__ out_w) {
    extern __shared__ float sm[];
    __shared__ float spart[8 * SPW_];
    __shared__ __align__(16) float se[8 * SPW_];   // warp-private rows

    const int b = blockIdx.y, blk = blockIdx.x, t = threadIdx.x;
    const int w = t >> 5, lane = t & 31;
    const int idx = b * NB_ + blk;
    const float* xb = x + (size_t)b * C_ * HW_ + (size_t)blk * (TPC_ * P_);
    const float mb = mask_b[0];

    // free center-tap packing: 32 taps per CTA
    if (t < 32) {
        int ti = idx * 32 + t;
        int o = ti >> 8, c = ti & 255;
        g_wc[ti] = __ldg(out_w + (size_t)o * (C_ * 25) + (size_t)c * 25 + 12);
    }

    // mask weights for this warp's 32 channels -> registers
    float wv[32];
    {
        float myw = mask_w[w * 32 + lane];
#pragma unroll
        for (int cc = 0; cc < 32; cc++)
            wv[cc] = __shfl_sync(0xffffffffu, myw, cc);
    }

    const unsigned smbase = smem_u32(sm);

    auto load_tile = [&](int tile, int slot) {
        const unsigned dbase = smbase + (unsigned)(slot * C_ * RP_) * 4u;
        const float* src0 = xb + tile * P_;
#pragma unroll
        for (int i = 0; i < 8; i++) {
            int s = i * 256 + t;
            int c = s >> 3, q = s & 7;
            cp16(dbase + (unsigned)(c * RP_ + q * 4) * 4u,
                 src0 + (size_t)c * HW_ + q * 4);
        }
    };

    load_tile(0, 0); cp_commit();
    load_tile(1, 1); cp_commit();

    float acc = 0.f;     // channel t partial context
    float zw  = 0.f;     // warp 0 only

    int slot = 0;
#pragma unroll 1
    for (int tile = 0; tile < TPC_; tile++) {
        if (tile < TPC_ - 1) cp_wait1();
        else                 cp_wait0();
        __syncthreads();                 // tile visible; slot (tile-1) released

        if (tile + 2 < TPC_) {
            int ns = slot + 2; if (ns >= NSLOT_) ns -= NSLOT_;
            load_tile(tile + 2, ns);
            cp_commit();
        }

        const float* buf = sm + slot * C_ * RP_;

        // logit partials: warp w -> channels [32w,32w+32), lane = position
        float lacc = 0.f;
#pragma unroll
        for (int cc = 0; cc < 32; cc++)
            lacc += buf[(w * 32 + cc) * RP_ + lane] * wv[cc];
        spart[w * SPW_ + lane] = lacc;
        __syncthreads();

        // exp: every warp redundantly computes all 32 e's (lane = position),
        // stores to its PRIVATE se row -> only __syncwarp needed.
        {
            float lg = mb;
#pragma unroll
            for (int g2 = 0; g2 < 8; g2++) lg += spart[g2 * SPW_ + lane];
            float e = __expf(lg);
            se[w * SPW_ + lane] = e;
            if (w == 0) {
                float z = e;
#pragma unroll
                for (int o = 16; o; o >>= 1)
                    z += __shfl_xor_sync(0xffffffffu, z, o);
                zw += z;
            }
            __syncwarp();
        }

        // context: thread t = channel t; e from this warp's private row
        const float4* rowv = reinterpret_cast<const float4*>(buf + t * RP_);
        const float4* sev  = reinterpret_cast<const float4*>(se + w * SPW_);
        float a0 = 0.f, a1 = 0.f;
#pragma unroll
        for (int pp = 0; pp < 8; pp++) {
            float4 xv = rowv[pp], ev = sev[pp];
            a0 += xv.x * ev.x + xv.y * ev.y;
            a1 += xv.z * ev.z + xv.w * ev.w;
        }
        acc += a0 + a1;

        slot++; if (slot >= NSLOT_) slot = 0;
    }

    g_part[(size_t)idx * C_ + t] = acc;
    if (t == 0) g_z[idx] = zw;
}

// ---------------------------------------------------------------------------
// mv1: grid(4, B). Combine ctx (redundant, L2-hot) + 64 rows of cm1.
// ---------------------------------------------------------------------------
__global__ __launch_bounds__(256)
void mv1_kernel(const float* __restrict__ cm1_w, const float* __restrict__ cm1_b) {
    __shared__ float sctx[C_];
    __shared__ float sred[1];

    const int b = blockIdx.y, rc = blockIdx.x, t = threadIdx.x;
    const int w = t >> 5, lane = t & 31;

    if (t < 32) {
        float zz = g_z[b * NB_ + t] + g_z[b * NB_ + 32 + t];
#pragma unroll
        for (int o = 16; o; o >>= 1) zz += __shfl_xor_sync(0xffffffffu, zz, o);
        if (t == 0) sred[0] = 1.f / zz;
    }

    float acc = 0.f;
    const float* gp = g_part + (size_t)b * NB_ * C_ + t;
#pragma unroll 8
    for (int k = 0; k < NB_; k++) acc += gp[(size_t)k * C_];
    __syncthreads();
    sctx[t] = acc * sred[0];
    __syncthreads();

#pragma unroll
    for (int i = 0; i < 4; i++) {
        int o0 = rc * 64 + w * 8 + 2 * i, o1 = o0 + 1;
        const float* r0 = cm1_w + (size_t)o0 * C_;
        const float* r1 = cm1_w + (size_t)o1 * C_;
        float p0 = 0.f, p1 = 0.f;
#pragma unroll
        for (int j = 0; j < 8; j++) {
            float v = sctx[j * 32 + lane];
            p0 += r0[j * 32 + lane] * v;
            p1 += r1[j * 32 + lane] * v;
        }
#pragma unroll
        for (int o = 16; o; o >>= 1) {
            p0 += __shfl_xor_sync(0xffffffffu, p0, o);
            p1 += __shfl_xor_sync(0xffffffffu, p1, o);
        }
        if (lane == 0) {
            g_h1[b * C_ + o0] = p0 + cm1_b[o0];
            g_h1[b * C_ + o1] = p1 + cm1_b[o1];
        }
    }
}

// ---------------------------------------------------------------------------
// mv2: grid(4, B). LN (redundant stats) + ReLU + 64 rows of cm2 + sigmoid.
// ---------------------------------------------------------------------------
__global__ __launch_bounds__(256)
void mv2_kernel(const float* __restrict__ ln_g,  const float* __restrict__ ln_b,
                const float* __restrict__ cm2_w, const float* __restrict__ cm2_b) {
    __shared__ float sh[C_];
    __shared__ float sred[18];

    const int b = blockIdx.y, rc = blockIdx.x, t = threadIdx.x;
    const int w = t >> 5, lane = t & 31;

    float h = g_h1[b * C_ + t];
    float sum = h, sq = h * h;
#pragma unroll
    for (int o = 16; o; o >>= 1) {
        sum += __shfl_xor_sync(0xffffffffu, sum, o);
        sq  += __shfl_xor_sync(0xffffffffu, sq,  o);
    }
    if (lane == 0) { sred[2 + w] = sum; sred[10 + w] = sq; }
    __syncthreads();
    if (t == 0) {
        float a = 0.f, bb = 0.f;
#pragma unroll
        for (int i = 0; i < 8; i++) { a += sred[2 + i]; bb += sred[10 + i]; }
        sred[0] = a; sred[1] = bb;
    }
    __syncthreads();
    {
        const float mu  = sred[0] * (1.f / C_);
        const float var = sred[1] * (1.f / C_) - mu * mu;
        h = (h - mu) * rsqrtf(var + 1e-5f) * ln_g[t] + ln_b[t];
        h = fmaxf(h, 0.f);
    }
    sh[t] = h;
    __syncthreads();

#pragma unroll
    for (int i = 0; i < 4; i++) {
        int o0 = rc * 64 + w * 8 + 2 * i, o1 = o0 + 1;
        const float* r0 = cm2_w + (size_t)o0 * C_;
        const float* r1 = cm2_w + (size_t)o1 * C_;
        float p0 = 0.f, p1 = 0.f;
#pragma unroll
        for (int j = 0; j < 8; j++) {
            float v = sh[j * 32 + lane];
            p0 += r0[j * 32 + lane] * v;
            p1 += r1[j * 32 + lane] * v;
        }
#pragma unroll
        for (int o = 16; o; o >>= 1) {
            p0 += __shfl_xor_sync(0xffffffffu, p0, o);
            p1 += __shfl_xor_sync(0xffffffffu, p1, o);
        }
        if (lane == 0) {
            g_ix[b * C_ + o0] = 1.f / (1.f + __expf(-(p0 + cm2_b[o0])));
            g_ix[b * C_ + o1] = 1.f / (1.f + __expf(-(p1 + cm2_b[o1])));
        }
    }
}

// ---------------------------------------------------------------------------
// gate: grid(128). CTA j owns features {2j, 2j+1} for all 32 batches.
// All weight reads coalesced (taps come packed from g_wc).
// ---------------------------------------------------------------------------
__global__ __launch_bounds__(256)
void gate_kernel(const float* __restrict__ out_b,
                 const float* __restrict__ att_w, const float* __restrict__ att_b,
                 float* __restrict__ out) {
    __shared__ float swa0[C_], swa1[C_], swc0[C_], swc1[C_];

    const int j = blockIdx.x, t = threadIdx.x;
    const int o0 = 2 * j, o1 = 2 * j + 1;
    const int w = t >> 5, lane = t & 31;

    swa0[t] = att_w[(size_t)o0 * C_ + t];
    swa1[t] = att_w[(size_t)o1 * C_ + t];
    swc0[t] = g_wc[o0 * C_ + t];
    swc1[t] = g_wc[o1 * C_ + t];
    __syncthreads();

#pragma unroll
    for (int bb = 0; bb < 4; bb++) {
        int b = w * 4 + bb;
        const float* ixp = g_ix + b * C_;
        float pa0 = 0.f, pa1 = 0.f, pc0 = 0.f, pc1 = 0.f;
#pragma unroll
        for (int k = 0; k < 8; k++) {
            int c = k * 32 + lane;
            float v = ixp[c];
            pa0 += swa0[c] * v;
            pa1 += swa1[c] * v;
            pc0 += swc0[c] * v;
            pc1 += swc1[c] * v;
        }
#pragma unroll
        for (int o = 16; o; o >>= 1) {
            pa0 += __shfl_xor_sync(0xffffffffu, pa0, o);
            pa1 += __shfl_xor_sync(0xffffffffu, pa1, o);
            pc0 += __shfl_xor_sync(0xffffffffu, pc0, o);
            pc1 += __shfl_xor_sync(0xffffffffu, pc1, o);
        }
        if (lane == 0) {
            float a0 = 1.f / (1.f + __expf(-(pa0 + att_b[o0])));
            float a1 = 1.f / (1.f + __expf(-(pa1 + att_b[o1])));
            out[b * F_ + o0] = a0 * (pc0 + out_b[o0]);
            out[b * F_ + o1] = a1 * (pc1 + out_b[o1]);
        }
    }
}

extern "C" void kernel_launch(void* const* d_in, const int* in_sizes, int n_in,
                              void* d_out, int out_size) {
    const float* x      = (const float*)d_in[0];
    const float* mask_w = (const float*)d_in[1];
    const float* mask_b = (const float*)d_in[2];
    const float* cm1_w  = (const float*)d_in[3];
    const float* cm1_b  = (const float*)d_in[4];
    const float* ln_g   = (const float*)d_in[5];
    const float* ln_b   = (const float*)d_in[6];
    const float* cm2_w  = (const float*)d_in[7];
    const float* cm2_b  = (const float*)d_in[8];
    const float* out_w  = (const float*)d_in[9];
    const float* out_b  = (const float*)d_in[10];
    const float* att_w  = (const float*)d_in[11];
    const float* att_b  = (const float*)d_in[12];
    float* out = (float*)d_out;

    const int smem1 = NSLOT_ * C_ * RP_ * (int)sizeof(float);  // 110592 B
    cudaFuncSetAttribute(ctx_pass1, cudaFuncAttributeMaxDynamicSharedMemorySize, smem1);

    ctx_pass1<<<dim3(NB_, B_), 256, smem1>>>(x, mask_w, mask_b, out_w);
    mv1_kernel<<<dim3(4, B_), 256>>>(cm1_w, cm1_b);
    mv2_kernel<<<dim3(4, B_), 256>>>(ln_g, ln_b, cm2_w, cm2_b);
    gate_kernel<<<128, 256>>>(out_b, att_w, att_b, out);
}